// round 4
// baseline (speedup 1.0000x reference)
#include <cuda_runtime.h>
#include <math.h>

// ---------------- problem constants ----------------
#define N_TOTAL   1000000
#define N_GATHER  200000
#define M_UPD     131072
#define MSG_DIM   512
#define DIM       256
#define G3        768          // 3 * DIM
#define LN_EPS    1e-5f

// ---------------- scratch (static device globals: allocation-free) ----------------
__device__ float g_gx[(size_t)M_UPD * G3];   // messages @ W_ih^T + b_ih
__device__ float g_gh[(size_t)M_UPD * G3];   // H        @ W_hh^T + b_hh
__device__ int   g_rid[M_UPD];               // node_ids[to_update[i]]

// ---------------- small helpers ----------------
__device__ __forceinline__ unsigned long long dup2(float v) {
    unsigned long long r;
    asm("mov.b64 %0, {%1, %1};" : "=l"(r) : "f"(v));
    return r;
}
__device__ __forceinline__ float2 u2f(unsigned long long u) {
    float2 f;
    asm("mov.b64 {%0, %1}, %2;" : "=f"(f.x), "=f"(f.y) : "l"(u));
    return f;
}
__device__ __forceinline__ float sigm(float x) { return 1.0f / (1.0f + expf(-x)); }

// ---------------- GEMM: C[M, 768] = A[M, K] @ B[768, K]^T + bias ----------------
// A rows optionally gathered through rowidx. Inner loop: packed fma.rn.f32x2
// (FFMA2, 2x fp32 rate on sm_103a); A pairs built with mov.b64 (alu pipe) so the
// smem crossbar carries only 32B A + 32B B per thread per k-step.
#define BM 128
#define BN 128
#define BK 16
#define PAD 4   // +4 floats per smem row: kills 4-way bank conflict on tile stores

__global__ __launch_bounds__(256, 2)
void sgemm_bias(const float* __restrict__ A,
                const float* __restrict__ B,
                const float* __restrict__ bias,
                float* __restrict__ C,
                int K,
                const int* __restrict__ rowidx)
{
    __shared__ __align__(16) float As[2][BK][BM + PAD];
    __shared__ __align__(16) float Bs[2][BK][BN + PAD];

    const int tid = threadIdx.x;
    const int bn  = blockIdx.x * BN;   // N fastest: the 6 N-tiles of one M-tile
    const int bm  = blockIdx.y * BM;   //   run together -> A rows hit in L2

    // global-load mapping: each thread loads 2 float4 of A and 2 float4 of B per tile
    const int lr  = tid >> 2;          // 0..63
    const int lc4 = tid & 3;           // float4 slot along K
    const int ar0 = lr, ar1 = lr + 64;

    size_t aoff0, aoff1;
    {
        const int gr0 = bm + ar0, gr1 = bm + ar1;
        const int i0 = rowidx ? rowidx[gr0] : gr0;
        const int i1 = rowidx ? rowidx[gr1] : gr1;
        aoff0 = (size_t)i0 * K + lc4 * 4;
        aoff1 = (size_t)i1 * K + lc4 * 4;
    }
    const size_t boff0 = (size_t)(bn + lr)      * K + lc4 * 4;
    const size_t boff1 = (size_t)(bn + lr + 64) * K + lc4 * 4;

    const int ty = tid >> 4, tx = tid & 15;
    const int m0 = ty * 8,  n0 = tx * 8;

    unsigned long long acc[8][4];
    #pragma unroll
    for (int i = 0; i < 8; i++)
        #pragma unroll
        for (int q = 0; q < 4; q++) acc[i][q] = 0ull;

    float4 a0 = *(const float4*)(A + aoff0);
    float4 a1 = *(const float4*)(A + aoff1);
    float4 b0 = *(const float4*)(B + boff0);
    float4 b1 = *(const float4*)(B + boff1);

#define STORE_TILE(BUF)                                                          \
    do { const int kb = lc4 * 4;                                                 \
        As[BUF][kb+0][ar0] = a0.x; As[BUF][kb+1][ar0] = a0.y;                    \
        As[BUF][kb+2][ar0] = a0.z; As[BUF][kb+3][ar0] = a0.w;                    \
        As[BUF][kb+0][ar1] = a1.x; As[BUF][kb+1][ar1] = a1.y;                    \
        As[BUF][kb+2][ar1] = a1.z; As[BUF][kb+3][ar1] = a1.w;                    \
        Bs[BUF][kb+0][lr   ] = b0.x; Bs[BUF][kb+1][lr   ] = b0.y;                \
        Bs[BUF][kb+2][lr   ] = b0.z; Bs[BUF][kb+3][lr   ] = b0.w;                \
        Bs[BUF][kb+0][lr+64] = b1.x; Bs[BUF][kb+1][lr+64] = b1.y;                \
        Bs[BUF][kb+2][lr+64] = b1.z; Bs[BUF][kb+3][lr+64] = b1.w;                \
    } while (0)

    STORE_TILE(0);
    __syncthreads();

    const int ktiles = K / BK;
    for (int kt = 0; kt < ktiles; ++kt) {
        const int  buf  = kt & 1;
        const bool more = (kt + 1) < ktiles;
        if (more) {
            const size_t ko = (size_t)(kt + 1) * BK;
            a0 = *(const float4*)(A + aoff0 + ko);
            a1 = *(const float4*)(A + aoff1 + ko);
            b0 = *(const float4*)(B + boff0 + ko);
            b1 = *(const float4*)(B + boff1 + ko);
        }
        #pragma unroll
        for (int kk = 0; kk < BK; ++kk) {
            // A: 2x LDS.128 (plain floats) + 8 mov.b64 dup -> pairs
            const float* ap = &As[buf][kk][m0];
            float4 af0 = *(const float4*)ap;
            float4 af1 = *(const float4*)(ap + 4);
            unsigned long long aa[8];
            aa[0] = dup2(af0.x); aa[1] = dup2(af0.y);
            aa[2] = dup2(af0.z); aa[3] = dup2(af0.w);
            aa[4] = dup2(af1.x); aa[5] = dup2(af1.y);
            aa[6] = dup2(af1.z); aa[7] = dup2(af1.w);
            // B: naturally packed n-pairs, 2x LDS.128
            const ulonglong2* bp = reinterpret_cast<const ulonglong2*>(&Bs[buf][kk][n0]);
            ulonglong2 u0 = bp[0], u1 = bp[1];
            unsigned long long bb[4] = { u0.x, u0.y, u1.x, u1.y };
            #pragma unroll
            for (int i = 0; i < 8; i++)
                #pragma unroll
                for (int q = 0; q < 4; q++)
                    asm volatile("fma.rn.f32x2 %0, %1, %2, %0;"
                                 : "+l"(acc[i][q]) : "l"(aa[i]), "l"(bb[q]));
        }
        if (more) {
            STORE_TILE(buf ^ 1);
            __syncthreads();
        }
    }
#undef STORE_TILE

    // epilogue: + bias, vectorized store
    float bv[8];
    #pragma unroll
    for (int j = 0; j < 8; j++) bv[j] = bias[bn + n0 + j];
    #pragma unroll
    for (int i = 0; i < 8; i++) {
        float2 v0 = u2f(acc[i][0]), v1 = u2f(acc[i][1]);
        float2 v2 = u2f(acc[i][2]), v3 = u2f(acc[i][3]);
        float4 o0 = make_float4(v0.x + bv[0], v0.y + bv[1], v1.x + bv[2], v1.y + bv[3]);
        float4 o1 = make_float4(v2.x + bv[4], v2.y + bv[5], v3.x + bv[6], v3.y + bv[7]);
        float* cp = C + (size_t)(bm + m0 + i) * G3 + bn + n0;
        *(float4*)cp       = o0;
        *(float4*)(cp + 4) = o1;
    }
}

// ---------------- passthrough: out = gather(memory_table / last_update) ----------------
__global__ void passthrough_kernel(const float* __restrict__ mt, const float* __restrict__ lu,
                                   const int* __restrict__ nid,
                                   float* __restrict__ out_mem, float* __restrict__ out_lu)
{
    const int row = blockIdx.x * 4 + (threadIdx.x >> 6);
    const int t   = threadIdx.x & 63;
    const int id  = nid[row];
    const float4 v = *(const float4*)(mt + (size_t)id * DIM + t * 4);
    *(float4*)(out_mem + (size_t)row * DIM + t * 4) = v;
    if (t == 0) out_lu[row] = lu[id];
}

// ---------------- rid[i] = node_ids[to_update[i]] ----------------
__global__ void make_rid_kernel(const int* __restrict__ nid, const int* __restrict__ tu,
                                int* __restrict__ rid)
{
    const int i = blockIdx.x * 256 + threadIdx.x;   // grid sized exactly to M_UPD
    rid[i] = nid[tu[i]];
}

// ---------------- fused GRU gates + LayerNorm + scatter ----------------
__global__ void epilogue_kernel(const float* __restrict__ gx, const float* __restrict__ gh,
                                const float* __restrict__ mt,
                                const float* __restrict__ gamma, const float* __restrict__ beta,
                                const int* __restrict__ rid, const int* __restrict__ tu,
                                const float* __restrict__ ts,
                                float* __restrict__ out_mem, float* __restrict__ out_lu)
{
    const int row = blockIdx.x;
    const int j   = threadIdx.x;     // 256 threads = one per feature
    const size_t base = (size_t)row * G3;

    const float xr = gx[base + j],        hr = gh[base + j];
    const float xz = gx[base + 256 + j],  hz = gh[base + 256 + j];
    const float xn = gx[base + 512 + j],  hn = gh[base + 512 + j];

    const float r = sigm(xr + hr);
    const float z = sigm(xz + hz);
    const float n = tanhf(xn + r * hn);
    const float h = mt[(size_t)rid[row] * DIM + j];
    const float hv = (1.0f - z) * n + z * h;

    // LayerNorm over 256 features
    float s = hv, s2 = hv * hv;
    #pragma unroll
    for (int o = 16; o > 0; o >>= 1) {
        s  += __shfl_xor_sync(0xffffffffu, s,  o);
        s2 += __shfl_xor_sync(0xffffffffu, s2, o);
    }
    __shared__ float ws[8], ws2[8];
    if ((j & 31) == 0) { ws[j >> 5] = s; ws2[j >> 5] = s2; }
    __syncthreads();
    float tot = 0.f, tot2 = 0.f;
    #pragma unroll
    for (int w = 0; w < 8; ++w) { tot += ws[w]; tot2 += ws2[w]; }
    const float mu  = tot  * (1.0f / 256.0f);
    const float var = tot2 * (1.0f / 256.0f) - mu * mu;
    const float inv = rsqrtf(var + LN_EPS);
    const float o   = (hv - mu) * inv * gamma[j] + beta[j];

    const int orow = tu[row];
    out_mem[(size_t)orow * DIM + j] = o;
    if (j == 0) out_lu[orow] = ts[row];
}

// ---------------- launch ----------------
extern "C" void kernel_launch(void* const* d_in, const int* in_sizes, int n_in,
                              void* d_out, int out_size)
{
    const float* mt    = (const float*)d_in[0];   // memory_table [1e6, 256]
    const float* lu    = (const float*)d_in[1];   // last_update  [1e6]
    const float* Wih   = (const float*)d_in[2];   // [768, 512]
    const float* Whh   = (const float*)d_in[3];   // [768, 256]
    const float* bih   = (const float*)d_in[4];   // [768]
    const float* bhh   = (const float*)d_in[5];   // [768]
    const float* gamma = (const float*)d_in[6];   // [256]
    const float* beta  = (const float*)d_in[7];   // [256]
    const float* msg   = (const float*)d_in[8];   // [131072, 512]
    const float* ts    = (const float*)d_in[9];   // [131072]
    const int*   nid   = (const int*)d_in[10];    // [200000]
    const int*   tu    = (const int*)d_in[11];    // [131072]

    float* out_mem = (float*)d_out;                       // [200000, 256]
    float* out_lu  = out_mem + (size_t)N_GATHER * DIM;    // [200000]

    float* pgx = nullptr; float* pgh = nullptr; int* prid = nullptr;
    cudaGetSymbolAddress((void**)&pgx,  g_gx);
    cudaGetSymbolAddress((void**)&pgh,  g_gh);
    cudaGetSymbolAddress((void**)&prid, g_rid);

    // 1) gather passthrough for all rows (updated rows overwritten later)
    passthrough_kernel<<<N_GATHER / 4, 256>>>(mt, lu, nid, out_mem, out_lu);

    // 2) row indices for the update subset
    make_rid_kernel<<<M_UPD / 256, 256>>>(nid, tu, prid);

    // 3) the two GEMMs
    dim3 gg(G3 / BN, M_UPD / BM);   // (6, 1024)
    sgemm_bias<<<gg, 256>>>(msg, Wih, bih, pgx, MSG_DIM, nullptr);
    sgemm_bias<<<gg, 256>>>(mt,  Whh, bhh, pgh, DIM,     prid);

    // 4) GRU gates + LayerNorm + scatter
    epilogue_kernel<<<M_UPD, 256>>>(pgx, pgh, mt, gamma, beta, prid, tu, ts, out_mem, out_lu);
}

// round 8
// speedup vs baseline: 1.8652x; 1.8652x over previous
#include <cuda_runtime.h>
#include <cuda_bf16.h>
#include <math.h>
#include <stdint.h>

// ---------------- problem constants ----------------
#define N_TOTAL   1000000
#define N_GATHER  200000
#define M_UPD     131072
#define MSG_DIM   512
#define DIM       256
#define G3        768
#define LN_EPS    1e-5f

#define KP_X (3 * MSG_DIM)   // 1536: packed K' for the msg GEMM
#define KP_H (3 * DIM)       // 768:  packed K' for the hidden GEMM

// ---------------- scratch (static device globals: allocation-free) ----------------
__device__ __nv_bfloat16 g_ax[(size_t)M_UPD * KP_X];  // row-major [M, K']  A' = [Ah|Ah|Al]
__device__ __nv_bfloat16 g_ah[(size_t)M_UPD * KP_H];
__device__ __nv_bfloat16 g_bx[(size_t)G3 * KP_X];     // row-major [N, K']  B' = [Bh|Bl|Bh]
__device__ __nv_bfloat16 g_bh[(size_t)G3 * KP_H];
__device__ float g_gx[(size_t)M_UPD * G3];
__device__ float g_gh[(size_t)M_UPD * G3];
__device__ int   g_rid[M_UPD];

// ---------------- helpers ----------------
__device__ __forceinline__ uint32_t smem_u32(const void* p) {
    uint32_t a;
    asm("{ .reg .u64 t; cvta.to.shared.u64 t, %1; cvt.u32.u64 %0, t; }" : "=r"(a) : "l"(p));
    return a;
}
__device__ __forceinline__ void cpa16(uint32_t dst, const void* src) {
    asm volatile("cp.async.cg.shared.global [%0], [%1], 16;" :: "r"(dst), "l"(src) : "memory");
}
__device__ __forceinline__ void ldsm4(uint32_t* r, uint32_t addr) {
    asm volatile("ldmatrix.sync.aligned.m8n8.x4.shared.b16 {%0,%1,%2,%3}, [%4];"
                 : "=r"(r[0]), "=r"(r[1]), "=r"(r[2]), "=r"(r[3]) : "r"(addr));
}
__device__ __forceinline__ void mma16816(float* d, const uint32_t* a, uint32_t b0, uint32_t b1) {
    asm volatile("mma.sync.aligned.m16n8k16.row.col.f32.bf16.bf16.f32 "
                 "{%0,%1,%2,%3}, {%4,%5,%6,%7}, {%8,%9}, {%0,%1,%2,%3};"
                 : "+f"(d[0]), "+f"(d[1]), "+f"(d[2]), "+f"(d[3])
                 : "r"(a[0]), "r"(a[1]), "r"(a[2]), "r"(a[3]), "r"(b0), "r"(b1));
}
__device__ __forceinline__ float sigm(float x) { return 1.0f / (1.0f + expf(-x)); }

// ==================================================================================
// Conversion: X[rows,K] fp32 (optionally row-gathered) -> bf16 hi/lo packed K'=3K.
//   bmode=0 (A operand): segments [hi | hi | lo]
//   bmode=1 (B operand): segments [hi | lo | hi]
// so that sum over K' = Ah*Bh + Ah*Bl + Al*Bh  (Al*Bl dropped, ~4e-6 rel).
// ==================================================================================
__global__ void conv_hilo(const float* __restrict__ src, const int* __restrict__ rowidx,
                          __nv_bfloat16* __restrict__ dst, int K, int bmode)
{
    const int q  = blockIdx.x * 256 + threadIdx.x;   // grid sized exactly: rows*K/4 threads
    const int kq = K >> 2;
    const int m  = q / kq;
    const int k  = (q - m * kq) << 2;

    const int srow = rowidx ? rowidx[m] : m;
    const float4 v = *(const float4*)(src + (size_t)srow * K + k);

    const __nv_bfloat16 h0 = __float2bfloat16(v.x);
    const __nv_bfloat16 h1 = __float2bfloat16(v.y);
    const __nv_bfloat16 h2 = __float2bfloat16(v.z);
    const __nv_bfloat16 h3 = __float2bfloat16(v.w);
    const __nv_bfloat16 l0 = __float2bfloat16(v.x - __bfloat162float(h0));
    const __nv_bfloat16 l1 = __float2bfloat16(v.y - __bfloat162float(h1));
    const __nv_bfloat16 l2 = __float2bfloat16(v.z - __bfloat162float(h2));
    const __nv_bfloat16 l3 = __float2bfloat16(v.w - __bfloat162float(h3));

    unsigned long long hq =  (unsigned long long)__bfloat16_as_ushort(h0)
                          | ((unsigned long long)__bfloat16_as_ushort(h1) << 16)
                          | ((unsigned long long)__bfloat16_as_ushort(h2) << 32)
                          | ((unsigned long long)__bfloat16_as_ushort(h3) << 48);
    unsigned long long lq =  (unsigned long long)__bfloat16_as_ushort(l0)
                          | ((unsigned long long)__bfloat16_as_ushort(l1) << 16)
                          | ((unsigned long long)__bfloat16_as_ushort(l2) << 32)
                          | ((unsigned long long)__bfloat16_as_ushort(l3) << 48);

    const int Kp = 3 * K;
    unsigned long long* drow = (unsigned long long*)(dst + (size_t)m * Kp);
    drow[k >> 2]            = hq;
    drow[(K + k) >> 2]      = bmode ? lq : hq;
    drow[(2 * K + k) >> 2]  = bmode ? hq : lq;
}

// ==================================================================================
// HMMA GEMM: C[M,768] = A[M,K'] @ B[768,K']^T + bias
// bf16 mma.sync m16n8k16 (row.col, TN), fp32 accum.
// CTA tile 128x128xBK32, 8 warps (4M x 2N, warp tile 32x64), 4-stage cp.async ring.
// SMEM rows padded to 40 bf16 (80B): conflict-free for cp.async stores and LDSM.
// ==================================================================================
#define STAGES    4
#define STAGE_B   10240u            // 128 rows * 80 bytes
#define SMEM_DYN  (2 * STAGES * STAGE_B)   // A ring + B ring = 81920 B

__global__ __launch_bounds__(256, 2)
void hmma_gemm(const __nv_bfloat16* __restrict__ A, const __nv_bfloat16* __restrict__ B,
               const float* __restrict__ bias, float* __restrict__ C, int nchunks)
{
    extern __shared__ char dsm[];
    __shared__ float sbias[128];

    const int tid = threadIdx.x, wid = tid >> 5, lane = tid & 31;
    const int Tn = blockIdx.x, Tm = blockIdx.y;
    const int Kp = nchunks * 32;

    if (tid < 128) sbias[tid] = bias[Tn * 128 + tid];

    const uint32_t smA = smem_u32(dsm);
    const uint32_t smB = smA + STAGES * STAGE_B;

    // ---- cp.async mapping: 512 16B-chunks per matrix per stage, 2 per thread ----
    const int r = tid >> 2, c = tid & 3;          // row 0..63(+64), 16B col chunk 0..3
    const __nv_bfloat16* aG0 = A + (size_t)(Tm * 128 + r) * Kp + c * 8;
    const __nv_bfloat16* bG0 = B + (size_t)(Tn * 128 + r) * Kp + c * 8;
    const __nv_bfloat16* aG1 = aG0 + (size_t)64 * Kp;
    const __nv_bfloat16* bG1 = bG0 + (size_t)64 * Kp;
    const uint32_t dA0 = smA + r * 80 + c * 16;
    const uint32_t dB0 = smB + r * 80 + c * 16;
    const uint32_t dA1 = dA0 + 64 * 80;
    const uint32_t dB1 = dB0 + 64 * 80;

#define ISSUE(kt)                                                                  \
    do { const uint32_t so_ = ((kt) & (STAGES - 1)) * STAGE_B;                     \
         const size_t go_ = (size_t)(kt) * 32;                                     \
         cpa16(dA0 + so_, aG0 + go_); cpa16(dA1 + so_, aG1 + go_);                 \
         cpa16(dB0 + so_, bG0 + go_); cpa16(dB1 + so_, bG1 + go_);                 \
         asm volatile("cp.async.commit_group;" ::: "memory"); } while (0)

    // ---- ldmatrix per-lane base addresses (byte offsets within a stage) ----
    const int wm = wid >> 1, wn = wid & 1;
    const int m0 = wm * 32,  n0 = wn * 64;
    // A x4: addr = &A[m0 + (lane%16)][ (lane/16)*8 ]  -> a0..a3 of m16k16
    const uint32_t aBase = smA + (m0 + (lane & 15)) * 80 + (lane >> 4) * 16;
    // B x4: addr = &B[n0 + ((lane>>4)&1)*8 + (lane&7)][ ((lane>>3)&1)*8 ]
    //   -> {b0,b1} for n-tile n0, {b0,b1} for n-tile n0+8 (one x4 = two n8 tiles)
    const uint32_t bBase = smB + (n0 + (((lane >> 4) & 1) * 8) + (lane & 7)) * 80
                               + (((lane >> 3) & 1) * 16);

    float acc[2][8][4];
    #pragma unroll
    for (int mi = 0; mi < 2; ++mi)
        #pragma unroll
        for (int ni = 0; ni < 8; ++ni)
            #pragma unroll
            for (int j = 0; j < 4; ++j) acc[mi][ni][j] = 0.f;

    ISSUE(0); ISSUE(1); ISSUE(2);     // nchunks >= 24 always

    for (int kt = 0; kt < nchunks; ++kt) {
        asm volatile("cp.async.wait_group 2;" ::: "memory");
        __syncthreads();
        if (kt + 3 < nchunks) ISSUE(kt + 3);

        const uint32_t so = (kt & (STAGES - 1)) * STAGE_B;
        #pragma unroll
        for (int k16 = 0; k16 < 2; ++k16) {
            uint32_t af[2][4];
            ldsm4(af[0], aBase + so + k16 * 32);
            ldsm4(af[1], aBase + so + k16 * 32 + 16 * 80);
            uint32_t bf[4][4];
            #pragma unroll
            for (int nj = 0; nj < 4; ++nj)
                ldsm4(bf[nj], bBase + so + k16 * 32 + nj * (16 * 80));
            #pragma unroll
            for (int mi = 0; mi < 2; ++mi)
                #pragma unroll
                for (int ni = 0; ni < 8; ++ni)
                    mma16816(acc[mi][ni], af[mi],
                             bf[ni >> 1][(ni & 1) * 2], bf[ni >> 1][(ni & 1) * 2 + 1]);
        }
    }
#undef ISSUE

    // ---- epilogue: + bias, write C ----
    const int g = lane >> 2, t = lane & 3;
    #pragma unroll
    for (int mi = 0; mi < 2; ++mi) {
        float* crow0 = C + (size_t)(Tm * 128 + m0 + mi * 16 + g) * G3 + Tn * 128 + n0;
        float* crow8 = crow0 + 8 * (size_t)G3;
        #pragma unroll
        for (int ni = 0; ni < 8; ++ni) {
            const int col = ni * 8 + 2 * t;
            const float b0 = sbias[n0 + col], b1 = sbias[n0 + col + 1];
            float2 v0 = make_float2(acc[mi][ni][0] + b0, acc[mi][ni][1] + b1);
            float2 v1 = make_float2(acc[mi][ni][2] + b0, acc[mi][ni][3] + b1);
            *(float2*)(crow0 + col) = v0;
            *(float2*)(crow8 + col) = v1;
        }
    }
}

// ---------------- passthrough: out = gather(memory_table / last_update) ----------------
__global__ void passthrough_kernel(const float* __restrict__ mt, const float* __restrict__ lu,
                                   const int* __restrict__ nid,
                                   float* __restrict__ out_mem, float* __restrict__ out_lu)
{
    const int row = blockIdx.x * 4 + (threadIdx.x >> 6);
    const int t   = threadIdx.x & 63;
    const int id  = nid[row];
    const float4 v = *(const float4*)(mt + (size_t)id * DIM + t * 4);
    *(float4*)(out_mem + (size_t)row * DIM + t * 4) = v;
    if (t == 0) out_lu[row] = lu[id];
}

// ---------------- rid[i] = node_ids[to_update[i]] ----------------
__global__ void make_rid_kernel(const int* __restrict__ nid, const int* __restrict__ tu,
                                int* __restrict__ rid)
{
    const int i = blockIdx.x * 256 + threadIdx.x;
    rid[i] = nid[tu[i]];
}

// ---------------- fused GRU gates + LayerNorm + scatter ----------------
__global__ void epilogue_kernel(const float* __restrict__ gx, const float* __restrict__ gh,
                                const float* __restrict__ mt,
                                const float* __restrict__ gamma, const float* __restrict__ beta,
                                const int* __restrict__ rid, const int* __restrict__ tu,
                                const float* __restrict__ ts,
                                float* __restrict__ out_mem, float* __restrict__ out_lu)
{
    const int row = blockIdx.x;
    const int j   = threadIdx.x;     // 256 threads = one per feature
    const size_t base = (size_t)row * G3;

    const float xr = gx[base + j],        hr = gh[base + j];
    const float xz = gx[base + 256 + j],  hz = gh[base + 256 + j];
    const float xn = gx[base + 512 + j],  hn = gh[base + 512 + j];

    const float r = sigm(xr + hr);
    const float z = sigm(xz + hz);
    const float n = tanhf(xn + r * hn);
    const float h = mt[(size_t)rid[row] * DIM + j];
    const float hv = (1.0f - z) * n + z * h;

    float s = hv, s2 = hv * hv;
    #pragma unroll
    for (int o = 16; o > 0; o >>= 1) {
        s  += __shfl_xor_sync(0xffffffffu, s,  o);
        s2 += __shfl_xor_sync(0xffffffffu, s2, o);
    }
    __shared__ float ws[8], ws2[8];
    if ((j & 31) == 0) { ws[j >> 5] = s; ws2[j >> 5] = s2; }
    __syncthreads();
    float tot = 0.f, tot2 = 0.f;
    #pragma unroll
    for (int w = 0; w < 8; ++w) { tot += ws[w]; tot2 += ws2[w]; }
    const float mu  = tot  * (1.0f / 256.0f);
    const float var = tot2 * (1.0f / 256.0f) - mu * mu;
    const float inv = rsqrtf(var + LN_EPS);
    const float o   = (hv - mu) * inv * gamma[j] + beta[j];

    const int orow = tu[row];
    out_mem[(size_t)orow * DIM + j] = o;
    if (j == 0) out_lu[orow] = ts[row];
}

// ---------------- launch ----------------
extern "C" void kernel_launch(void* const* d_in, const int* in_sizes, int n_in,
                              void* d_out, int out_size)
{
    const float* mt    = (const float*)d_in[0];   // memory_table [1e6, 256]
    const float* lu    = (const float*)d_in[1];   // last_update  [1e6]
    const float* Wih   = (const float*)d_in[2];   // [768, 512]
    const float* Whh   = (const float*)d_in[3];   // [768, 256]
    const float* bih   = (const float*)d_in[4];   // [768]
    const float* bhh   = (const float*)d_in[5];   // [768]
    const float* gamma = (const float*)d_in[6];   // [256]
    const float* beta  = (const float*)d_in[7];   // [256]
    const float* msg   = (const float*)d_in[8];   // [131072, 512]
    const float* ts    = (const float*)d_in[9];   // [131072]
    const int*   nid   = (const int*)d_in[10];    // [200000]
    const int*   tu    = (const int*)d_in[11];    // [131072]

    float* out_mem = (float*)d_out;                       // [200000, 256]
    float* out_lu  = out_mem + (size_t)N_GATHER * DIM;    // [200000]

    __nv_bfloat16 *pax, *pah, *pbx, *pbh;
    float *pgx, *pgh; int* prid;
    cudaGetSymbolAddress((void**)&pax,  g_ax);
    cudaGetSymbolAddress((void**)&pah,  g_ah);
    cudaGetSymbolAddress((void**)&pbx,  g_bx);
    cudaGetSymbolAddress((void**)&pbh,  g_bh);
    cudaGetSymbolAddress((void**)&pgx,  g_gx);
    cudaGetSymbolAddress((void**)&pgh,  g_gh);
    cudaGetSymbolAddress((void**)&prid, g_rid);

    cudaFuncSetAttribute(hmma_gemm, cudaFuncAttributeMaxDynamicSharedMemorySize, SMEM_DYN);

    // 1) gather passthrough for all rows (updated rows overwritten later)
    passthrough_kernel<<<N_GATHER / 4, 256>>>(mt, lu, nid, out_mem, out_lu);

    // 2) row indices for the update subset
    make_rid_kernel<<<M_UPD / 256, 256>>>(nid, tu, prid);

    // 3) bf16 hi/lo conversions (row-major packed K' = 3K)
    //    A operands: [hi|hi|lo]   B operands (weights): [hi|lo|hi]
    conv_hilo<<<(M_UPD * (MSG_DIM / 4)) / 256, 256>>>(msg, nullptr, pax, MSG_DIM, 0);
    conv_hilo<<<(M_UPD * (DIM     / 4)) / 256, 256>>>(mt,  prid,    pah, DIM,     0);
    conv_hilo<<<(G3    * (MSG_DIM / 4)) / 256, 256>>>(Wih, nullptr, pbx, MSG_DIM, 1);
    conv_hilo<<<(G3    * (DIM     / 4)) / 256, 256>>>(Whh, nullptr, pbh, DIM,     1);

    // 4) the two tensor-core GEMMs (K' = 1536 -> 48 chunks; K' = 768 -> 24 chunks)
    dim3 gg(G3 / 128, M_UPD / 128);   // (6, 1024)
    hmma_gemm<<<gg, 256, SMEM_DYN>>>(pax, pbx, bih, pgx, KP_X / 32);
    hmma_gemm<<<gg, 256, SMEM_DYN>>>(pah, pbh, bhh, pgh, KP_H / 32);

    // 5) GRU gates + LayerNorm + scatter
    epilogue_kernel<<<M_UPD, 256>>>(pgx, pgh, mt, gamma, beta, prid, tu, ts, out_mem, out_lu);
}